// round 16
// baseline (speedup 1.0000x reference)
#include <cuda_runtime.h>
#include <cuda_bf16.h>
#include <cstdint>
#include <math.h>

// 3 stacked dilated LSTM layers (rates 1,2,4), T=512, B=128, H=D=256, fp32 I/O.
// presplit(X,W) -> gemm gx = X@Wih^T + b (cp.async 2-stage pipeline) ->
// recurrent scan. Layers 0/1: fused 8 gate-CTAs x 1024 threads (recurF).
// Layer 2: 16 gate-CTAs x 512 threads (recur<4>), separate flag bank.

#define Hc    256
#define BATCH 128
#define TT    512
#define URS2  264            // u row stride (bf16 elems)
#define PRS   68             // part row stride (floats), recur<4>
#define PPL   (64 * PRS)
#define GXS   72             // gemm smem k-stride (shorts)
#define BUFSH (4 * 128 * GXS)

__device__ float          g_gx[(size_t)TT * BATCH * 1024];   // 256 MB
__device__ unsigned short g_hh[2][512 * 256];                // h hi plane (bf16)
__device__ unsigned short g_hl[2][512 * 256];                // h lo plane (bf16)
__device__ unsigned short g_xh[(size_t)TT * BATCH * 256];
__device__ unsigned short g_xl[(size_t)TT * BATCH * 256];
__device__ unsigned short g_wh[1024 * 256];
__device__ unsigned short g_wl[1024 * 256];
__device__ unsigned       g_flag[8][32 * 32];                // 2 banks x 16 flags

__device__ __forceinline__ void flag_set(unsigned* p, unsigned v) {
    asm volatile("st.release.gpu.global.u32 [%0], %1;" :: "l"(p), "r"(v) : "memory");
}
__device__ __forceinline__ unsigned flag_get(unsigned* p) {
    unsigned v;
    asm volatile("ld.acquire.gpu.global.u32 %0, [%1];" : "=r"(v) : "l"(p) : "memory");
    return v;
}
__device__ __forceinline__ unsigned smem_u32(const void* p) {
    unsigned a;
    asm("{ .reg .u64 t; cvta.to.shared.u64 t, %1; cvt.u32.u64 %0, t; }"
        : "=r"(a) : "l"(p));
    return a;
}
__device__ __forceinline__ void cp16(unsigned dst, const void* src) {
    asm volatile("cp.async.ca.shared.global [%0], [%1], 16;"
                 :: "r"(dst), "l"(src) : "memory");
}
__device__ __forceinline__ float ftanh_(float x) {
    float y;
    asm("tanh.approx.f32 %0, %1;" : "=f"(y) : "f"(x));
    return y;
}
__device__ __forceinline__ float fsig_(float x) {
    float e, y;
    asm("ex2.approx.ftz.f32 %0, %1;" : "=f"(e) : "f"(-1.4426950408889634f * x));
    asm("rcp.approx.ftz.f32 %0, %1;" : "=f"(y) : "f"(1.0f + e));
    return y;
}
__device__ __forceinline__ void split_pack(float x, float y,
                                           unsigned& hi, unsigned& lo) {
    __nv_bfloat162 h2, l2;
    h2.x = __float2bfloat16(x);
    h2.y = __float2bfloat16(y);
    l2.x = __float2bfloat16(x - __bfloat162float(h2.x));
    l2.y = __float2bfloat16(y - __bfloat162float(h2.y));
    hi = *(unsigned*)&h2;
    lo = *(unsigned*)&l2;
}
__device__ __forceinline__ void mma16816(float d[4], const unsigned a[4],
                                         unsigned b0, unsigned b1) {
    asm volatile(
        "mma.sync.aligned.m16n8k16.row.col.f32.bf16.bf16.f32 "
        "{%0,%1,%2,%3},{%4,%5,%6,%7},{%8,%9},{%0,%1,%2,%3};"
        : "+f"(d[0]), "+f"(d[1]), "+f"(d[2]), "+f"(d[3])
        : "r"(a[0]), "r"(a[1]), "r"(a[2]), "r"(a[3]), "r"(b0), "r"(b1));
}

// ============================================================================
// presplit: fp32 -> bf16 hi/lo planes
// ============================================================================
extern "C" __global__ void __launch_bounds__(512, 2)
presplit(const float* __restrict__ src, unsigned* __restrict__ dh,
         unsigned* __restrict__ dl, int n2)
{
    int i = blockIdx.x * 512 + threadIdx.x;
    if (i < n2) {
        float2 v = ((const float2*)src)[i];
        unsigned h, l;
        split_pack(v.x, v.y, h, l);
        dh[i] = h;
        dl[i] = l;
    }
}

// ============================================================================
// gemm: g_gx[row, R] = sum_k X[row,k]*W[R,k] + b1[R] + b2[R]
// grid (8, 512), cp.async 2-stage k-panel pipeline
// ============================================================================
extern "C" __global__ void __launch_bounds__(512, 1)
gemm_gx(const float* __restrict__ b1, const float* __restrict__ b2)
{
    extern __shared__ char smraw[];
    unsigned short* buf = (unsigned short*)smraw;
    float* bias_s = (float*)(buf + 2 * BUFSH);
    const unsigned sbase = smem_u32(smraw);

    const int bn = blockIdx.x, bm = blockIdx.y;
    const int tid  = threadIdx.x;
    const int wid  = tid >> 5, lane = tid & 31;
    const int wm   = wid >> 2, wn = wid & 3;
    const int gid  = lane >> 2, t4 = lane & 3;

    if (tid < 128) bias_s[tid] = b1[bn * 128 + tid] + b2[bn * 128 + tid];

    float dd[2][4][4];
    #pragma unroll
    for (int mt = 0; mt < 2; ++mt)
        #pragma unroll
        for (int nt = 0; nt < 4; ++nt)
            #pragma unroll
            for (int r = 0; r < 4; ++r) dd[mt][nt][r] = 0.f;

    const int r_ld = tid >> 2;
    const int p_ld = tid & 3;
    const size_t xoff = (size_t)(bm * 128 + r_ld) * 256;
    const size_t woff = (size_t)(bn * 128 + r_ld) * 256;

    auto prefetch = [&](int kp, int stage) {
        int kg = kp * 64 + p_ld * 16;
        int kl = p_ld * 16;
        unsigned db = sbase + (unsigned)(stage * BUFSH * 2);
        unsigned ro = (unsigned)((r_ld * GXS + kl) * 2);
        cp16(db + 0 * 128 * GXS * 2 + ro,      g_xh + xoff + kg);
        cp16(db + 0 * 128 * GXS * 2 + ro + 16, g_xh + xoff + kg + 8);
        cp16(db + 1 * 128 * GXS * 2 + ro,      g_xl + xoff + kg);
        cp16(db + 1 * 128 * GXS * 2 + ro + 16, g_xl + xoff + kg + 8);
        cp16(db + 2 * 128 * GXS * 2 + ro,      g_wh + woff + kg);
        cp16(db + 2 * 128 * GXS * 2 + ro + 16, g_wh + woff + kg + 8);
        cp16(db + 3 * 128 * GXS * 2 + ro,      g_wl + woff + kg);
        cp16(db + 3 * 128 * GXS * 2 + ro + 16, g_wl + woff + kg + 8);
        asm volatile("cp.async.commit_group;" ::: "memory");
    };

    prefetch(0, 0);

    for (int kp = 0; kp < 4; ++kp) {
        if (kp < 3) prefetch(kp + 1, (kp + 1) & 1);
        if (kp < 3) asm volatile("cp.async.wait_group 1;" ::: "memory");
        else        asm volatile("cp.async.wait_group 0;" ::: "memory");
        __syncthreads();

        unsigned short* Xh = buf + (kp & 1) * BUFSH;
        unsigned short* Xl = Xh + 128 * GXS;
        unsigned short* Wh = Xl + 128 * GXS;
        unsigned short* Wl = Wh + 128 * GXS;

        #pragma unroll
        for (int i = 0; i < 4; ++i) {
            int k0 = i * 16 + t4 * 2;
            unsigned ah[2][4], al[2][4];
            #pragma unroll
            for (int mt = 0; mt < 2; ++mt) {
                int r0 = wm * 32 + mt * 16;
                ah[mt][0] = *(unsigned*)(Xh + (r0 + gid)     * GXS + k0);
                ah[mt][1] = *(unsigned*)(Xh + (r0 + gid + 8) * GXS + k0);
                ah[mt][2] = *(unsigned*)(Xh + (r0 + gid)     * GXS + k0 + 8);
                ah[mt][3] = *(unsigned*)(Xh + (r0 + gid + 8) * GXS + k0 + 8);
                al[mt][0] = *(unsigned*)(Xl + (r0 + gid)     * GXS + k0);
                al[mt][1] = *(unsigned*)(Xl + (r0 + gid + 8) * GXS + k0);
                al[mt][2] = *(unsigned*)(Xl + (r0 + gid)     * GXS + k0 + 8);
                al[mt][3] = *(unsigned*)(Xl + (r0 + gid + 8) * GXS + k0 + 8);
            }
            #pragma unroll
            for (int nt = 0; nt < 4; ++nt) {
                int n0 = wn * 32 + nt * 8;
                unsigned bh0 = *(unsigned*)(Wh + (n0 + gid) * GXS + k0);
                unsigned bh1 = *(unsigned*)(Wh + (n0 + gid) * GXS + k0 + 8);
                unsigned bl0 = *(unsigned*)(Wl + (n0 + gid) * GXS + k0);
                unsigned bl1 = *(unsigned*)(Wl + (n0 + gid) * GXS + k0 + 8);
                #pragma unroll
                for (int mt = 0; mt < 2; ++mt) {
                    mma16816(dd[mt][nt], ah[mt], bh0, bh1);
                    mma16816(dd[mt][nt], ah[mt], bl0, bl1);
                    mma16816(dd[mt][nt], al[mt], bh0, bh1);
                }
            }
        }
        __syncthreads();
    }

    #pragma unroll
    for (int mt = 0; mt < 2; ++mt)
        #pragma unroll
        for (int nt = 0; nt < 4; ++nt) {
            int rowA = bm * 128 + wm * 32 + mt * 16 + gid;
            int cl   = wn * 32 + nt * 8 + 2 * t4;
            int col  = bn * 128 + cl;
            float bx = bias_s[cl], by = bias_s[cl + 1];
            *(float2*)(g_gx + (size_t)rowA * 1024 + col) =
                make_float2(dd[mt][nt][0] + bx, dd[mt][nt][1] + by);
            *(float2*)(g_gx + (size_t)(rowA + 8) * 1024 + col) =
                make_float2(dd[mt][nt][2] + bx, dd[mt][nt][3] + by);
        }
}

// ============================================================================
// recurF: FUSED layers 0/1. grid (8 gate-CTAs, 8 batch-blocks), 1024 threads.
// Warp (q,ks,cg): gate quadrant q, k-slice ks, col-half cg. cg==0 warps poll
// (2 producer flags) + stage; named bar per ks-group (8 warps); all warps MMA.
// ============================================================================
template<int NT16>
__global__ void __launch_bounds__(1024, 1)
recurF(const float* __restrict__ WhhL, float* __restrict__ out,
       int layer, int rate, int Td, unsigned stepBase)
{
    constexpr int Nper = NT16 * 16;
    constexpr int ELEM = NT16 * 512;            // n x 32 cols
    constexpr int PRSF = NT16 * 16 + 4;
    constexpr int PPLF = 128 * PRSF;

    extern __shared__ char smraw[];
    unsigned short* u_hi = (unsigned short*)smraw;        // Nper x URS2
    unsigned short* u_lo = u_hi + Nper * URS2;
    float* part = (float*)(smraw + (size_t)2 * Nper * URS2 * 2);  // 4 x PPLF

    const int g   = blockIdx.x;                 // 0..7: cols [32g, 32g+32)
    const int nb  = blockIdx.y;
    const int tid = threadIdx.x;
    const int wid = tid >> 5, lane = tid & 31;
    const int q   = wid & 3;
    const int ks  = (wid >> 2) & 3;
    const int cg  = wid >> 4;                   // col-half 0/1
    const int gid = lane >> 2, t4 = lane & 3;
    const int nG0 = nb * Nper;
    const int g2  = g * 2 + cg;                 // 16-col block index

    // stationary A fragments from Whh (K=256), gate-block g2
    unsigned a_hi[4][4], a_lo[4][4];
    {
        const int rowT = q * 256 + g2 * 16 + gid;
        const int rowB = rowT + 8;
        #pragma unroll
        for (int i = 0; i < 4; ++i) {
            int kb = (ks * 4 + i) * 16 + t4 * 2;
            #pragma unroll
            for (int r = 0; r < 4; ++r) {
                int row = (r & 1) ? rowB : rowT;
                int k   = kb + ((r >> 1) ? 8 : 0);
                float2 v = *(const float2*)(WhhL + (size_t)row * 256 + k);
                split_pack(v.x, v.y, a_hi[i][r], a_lo[i][r]);
            }
        }
    }

    unsigned* flags = &g_flag[nb][0];

    float gxp[4], creg = 0.f, hsv = 0.f;
    const int pe_n  = tid >> 5;                 // pointwise n (ELEM=1024 max)
    const int pe_jc = tid & 31;                 // local col 0..31
    const int pe_on = (tid < ELEM);

    // prefetch gx for step 0
    if (pe_on) {
        int nG = nG0 + pe_n;
        int rr = nG >> 7, bat = nG & 127;
        const float* gp = g_gx + ((size_t)(rr * BATCH + bat)) * 1024 + g * 32 + pe_jc;
        #pragma unroll
        for (int qq = 0; qq < 4; ++qq) gxp[qq] = gp[qq * 256];
    }

    for (int s = 0; s < Td; ++s) {
        if (s > 0) {
            // cg==0 warps: wait for the 2 producer CTAs of k-slice ks, stage
            if (cg == 0) {
                if (lane < 2) {
                    unsigned target = stepBase + (unsigned)s;
                    while (flag_get(&flags[(2 * ks + lane) * 32]) < target) { }
                }
                __syncwarp();
                const unsigned short* shh = g_hh[(s + 1) & 1];
                const unsigned short* shl = g_hl[(s + 1) & 1];
                #pragma unroll
                for (int it = 0; it < NT16; ++it) {
                    int row  = q * 4 * NT16 + it * 4 + (lane >> 3);
                    int kpos = ks * 64 + (lane & 7) * 8;
                    int nG   = nG0 + row;
                    uint4 vh = *(const uint4*)(shh + (size_t)nG * 256 + kpos);
                    uint4 vl = *(const uint4*)(shl + (size_t)nG * 256 + kpos);
                    *(uint4*)(u_hi + row * URS2 + kpos) = vh;
                    *(uint4*)(u_lo + row * URS2 + kpos) = vl;
                }
            }
            // sync the 8 warps of this ks-group (barrier ids 1..4)
            asm volatile("bar.sync %0, %1;" :: "r"(1 + ks), "r"(256) : "memory");

            // ---- HMMA: part = h @ Whh^T (split x3), k-slice ks, cols g2
            {
                float dd[NT16][8];
                #pragma unroll
                for (int nt = 0; nt < NT16; ++nt)
                    #pragma unroll
                    for (int r = 0; r < 8; ++r) dd[nt][r] = 0.f;

                #pragma unroll
                for (int i = 0; i < 4; ++i) {
                    int kof = (ks * 4 + i) * 16 + t4 * 2;
                    #pragma unroll
                    for (int nt = 0; nt < NT16; ++nt) {
                        const unsigned short* uh = u_hi + (nt * 16 + gid) * URS2 + kof;
                        const unsigned short* ul = u_lo + (nt * 16 + gid) * URS2 + kof;
                        unsigned bh0a = *(const unsigned*)uh;
                        unsigned bh0b = *(const unsigned*)(uh + 8);
                        unsigned bl0a = *(const unsigned*)ul;
                        unsigned bl0b = *(const unsigned*)(ul + 8);
                        unsigned bh8a = *(const unsigned*)(uh + 8 * URS2);
                        unsigned bh8b = *(const unsigned*)(uh + 8 * URS2 + 8);
                        unsigned bl8a = *(const unsigned*)(ul + 8 * URS2);
                        unsigned bl8b = *(const unsigned*)(ul + 8 * URS2 + 8);
                        mma16816(dd[nt] + 0, a_hi[i], bh0a, bh0b);
                        mma16816(dd[nt] + 0, a_hi[i], bl0a, bl0b);
                        mma16816(dd[nt] + 0, a_lo[i], bh0a, bh0b);
                        mma16816(dd[nt] + 4, a_hi[i], bh8a, bh8b);
                        mma16816(dd[nt] + 4, a_hi[i], bl8a, bl8b);
                        mma16816(dd[nt] + 4, a_lo[i], bh8a, bh8b);
                    }
                }

                // part rows: q*32 + cg*16 + {gid, gid+8}
                #pragma unroll
                for (int nt = 0; nt < NT16; ++nt) {
                    float* pp = part + ks * PPLF + (q * 32 + cg * 16) * PRSF + nt * 16;
                    *(float2*)(pp + gid * PRSF + 2 * t4)           = make_float2(dd[nt][0], dd[nt][1]);
                    *(float2*)(pp + (gid + 8) * PRSF + 2 * t4)     = make_float2(dd[nt][2], dd[nt][3]);
                    *(float2*)(pp + gid * PRSF + 8 + 2 * t4)       = make_float2(dd[nt][4], dd[nt][5]);
                    *(float2*)(pp + (gid + 8) * PRSF + 8 + 2 * t4) = make_float2(dd[nt][6], dd[nt][7]);
                }
            }
            __syncthreads();
        }

        // ---- pointwise: one (n, jc) per thread; c,h in regs; store h planes
        if (pe_on) {
            float gv[4];
            #pragma unroll
            for (int qq = 0; qq < 4; ++qq) {
                float v = gxp[qq];
                if (s > 0) {
                    const float* pq = part + (qq * 32 + pe_jc) * PRSF + pe_n;
                    #pragma unroll
                    for (int sp = 0; sp < 4; ++sp) v += pq[sp * PPLF];
                }
                gv[qq] = v;
            }
            float ig = fsig_(gv[0]);
            float fg = fsig_(gv[1]);
            float gt = ftanh_(gv[2]);
            float og = fsig_(gv[3]);
            float cnew = fg * creg + ig * gt;
            float hnew = og * ftanh_(cnew);
            creg = cnew;
            hsv  = hnew;

            int nG = nG0 + pe_n;
            int jcol = g * 32 + pe_jc;
            size_t sidx = (size_t)nG * 256 + jcol;
            __nv_bfloat16 hh = __float2bfloat16(hnew);
            __nv_bfloat16 hl = __float2bfloat16(hnew - __bfloat162float(hh));
            g_hh[s & 1][sidx] = *(unsigned short*)&hh;
            g_hl[s & 1][sidx] = *(unsigned short*)&hl;
        }
        __syncthreads();
        if (tid == 0) flag_set(&flags[g * 32], stepBase + (unsigned)(s + 1));

        // ---- shadowed behind barrier: out store + next-step gx prefetch
        if (pe_on) {
            int nG = nG0 + pe_n;
            int rr = nG >> 7, bat = nG & 127;
            int time = s * rate + rr;
            int jcol = g * 32 + pe_jc;
            out[((size_t)(layer * TT + time) * BATCH + bat) * Hc + jcol] = hsv;
            if (s + 1 < Td) {
                int time2 = (s + 1) * rate + rr;
                const float* gp = g_gx + ((size_t)(time2 * BATCH + bat)) * 1024 + jcol;
                #pragma unroll
                for (int qq = 0; qq < 4; ++qq) gxp[qq] = gp[qq * 256];
            }
        }
    }
}

// ============================================================================
// recur: layer 2. grid (16 gate-CTAs, 8 batch-blocks), 512 threads. NT16=4.
// Uses flag bank 1 (offset 16*32).
// ============================================================================
template<int NT16>
__global__ void __launch_bounds__(512, 1)
recur(const float* __restrict__ WhhL, float* __restrict__ out,
      int layer, int rate, int Td, unsigned stepBase)
{
    constexpr int Nper = NT16 * 16;
    constexpr int ELEM = NT16 * 256;
    constexpr int REPS = (ELEM + 511) / 512;

    extern __shared__ char smraw[];
    unsigned short* u_hi = (unsigned short*)smraw;
    unsigned short* u_lo = u_hi + Nper * URS2;
    float* part = (float*)(smraw + (size_t)2 * Nper * URS2 * 2);

    const int g   = blockIdx.x;
    const int nb  = blockIdx.y;
    const int tid = threadIdx.x;
    const int wid = tid >> 5, lane = tid & 31;
    const int q   = wid & 3;
    const int ks  = wid >> 2;
    const int gid = lane >> 2, t4 = lane & 3;
    const int nG0 = nb * Nper;

    unsigned a_hi[4][4], a_lo[4][4];
    {
        const int rowT = q * 256 + g * 16 + gid;
        const int rowB = rowT + 8;
        #pragma unroll
        for (int i = 0; i < 4; ++i) {
            int kb = (ks * 4 + i) * 16 + t4 * 2;
            #pragma unroll
            for (int r = 0; r < 4; ++r) {
                int row = (r & 1) ? rowB : rowT;
                int k   = kb + ((r >> 1) ? 8 : 0);
                float2 v = *(const float2*)(WhhL + (size_t)row * 256 + k);
                split_pack(v.x, v.y, a_hi[i][r], a_lo[i][r]);
            }
        }
    }

    unsigned* flags = &g_flag[nb][16 * 32];     // bank 1

    float gxp[REPS][4], creg[REPS], hsv[REPS];
    #pragma unroll
    for (int rep = 0; rep < REPS; ++rep) creg[rep] = 0.f;

    #pragma unroll
    for (int rep = 0; rep < REPS; ++rep) {
        int e = tid + 512 * rep;
        if (e < ELEM) {
            int n = e >> 4, jl = e & 15;
            int nG = nG0 + n;
            int rr = nG >> 7, bat = nG & 127;
            const float* gp = g_gx + ((size_t)(rr * BATCH + bat)) * 1024 + g * 16 + jl;
            #pragma unroll
            for (int qq = 0; qq < 4; ++qq) gxp[rep][qq] = gp[qq * 256];
        }
    }

    for (int s = 0; s < Td; ++s) {
        if (s > 0) {
            if (lane < 4) {
                unsigned target = stepBase + (unsigned)s;
                while (flag_get(&flags[(4 * ks + lane) * 32]) < target) { }
            }
            __syncwarp();

            {
                const unsigned short* shh = g_hh[(s + 1) & 1];
                const unsigned short* shl = g_hl[(s + 1) & 1];
                #pragma unroll
                for (int it = 0; it < NT16; ++it) {
                    int row  = q * 4 * NT16 + it * 4 + (lane >> 3);
                    int kpos = ks * 64 + (lane & 7) * 8;
                    int nG   = nG0 + row;
                    uint4 vh = *(const uint4*)(shh + (size_t)nG * 256 + kpos);
                    uint4 vl = *(const uint4*)(shl + (size_t)nG * 256 + kpos);
                    *(uint4*)(u_hi + row * URS2 + kpos) = vh;
                    *(uint4*)(u_lo + row * URS2 + kpos) = vl;
                }
            }
            asm volatile("bar.sync %0, %1;" :: "r"(1 + ks), "r"(128) : "memory");

            {
                float dd[NT16][8];
                #pragma unroll
                for (int nt = 0; nt < NT16; ++nt)
                    #pragma unroll
                    for (int r = 0; r < 8; ++r) dd[nt][r] = 0.f;

                #pragma unroll
                for (int i = 0; i < 4; ++i) {
                    int kof = (ks * 4 + i) * 16 + t4 * 2;
                    #pragma unroll
                    for (int nt = 0; nt < NT16; ++nt) {
                        const unsigned short* uh = u_hi + (nt * 16 + gid) * URS2 + kof;
                        const unsigned short* ul = u_lo + (nt * 16 + gid) * URS2 + kof;
                        unsigned bh0a = *(const unsigned*)uh;
                        unsigned bh0b = *(const unsigned*)(uh + 8);
                        unsigned bl0a = *(const unsigned*)ul;
                        unsigned bl0b = *(const unsigned*)(ul + 8);
                        unsigned bh8a = *(const unsigned*)(uh + 8 * URS2);
                        unsigned bh8b = *(const unsigned*)(uh + 8 * URS2 + 8);
                        unsigned bl8a = *(const unsigned*)(ul + 8 * URS2);
                        unsigned bl8b = *(const unsigned*)(ul + 8 * URS2 + 8);
                        mma16816(dd[nt] + 0, a_hi[i], bh0a, bh0b);
                        mma16816(dd[nt] + 0, a_hi[i], bl0a, bl0b);
                        mma16816(dd[nt] + 0, a_lo[i], bh0a, bh0b);
                        mma16816(dd[nt] + 4, a_hi[i], bh8a, bh8b);
                        mma16816(dd[nt] + 4, a_hi[i], bl8a, bl8b);
                        mma16816(dd[nt] + 4, a_lo[i], bh8a, bh8b);
                    }
                }

                #pragma unroll
                for (int nt = 0; nt < NT16; ++nt) {
                    float* pp = part + ks * PPL + (q * 16) * PRS + nt * 16;
                    *(float2*)(pp + gid * PRS + 2 * t4)           = make_float2(dd[nt][0], dd[nt][1]);
                    *(float2*)(pp + (gid + 8) * PRS + 2 * t4)     = make_float2(dd[nt][2], dd[nt][3]);
                    *(float2*)(pp + gid * PRS + 8 + 2 * t4)       = make_float2(dd[nt][4], dd[nt][5]);
                    *(float2*)(pp + (gid + 8) * PRS + 8 + 2 * t4) = make_float2(dd[nt][6], dd[nt][7]);
                }
            }
            __syncthreads();
        }

        {
            unsigned short* dhh = g_hh[s & 1];
            unsigned short* dhl = g_hl[s & 1];
            #pragma unroll
            for (int rep = 0; rep < REPS; ++rep) {
                int e = tid + 512 * rep;
                if (e < ELEM) {
                    int n = e >> 4, jl = e & 15;
                    int nG = nG0 + n;
                    float gv[4];
                    #pragma unroll
                    for (int qq = 0; qq < 4; ++qq) {
                        float v = gxp[rep][qq];
                        if (s > 0) {
                            const float* pq = part + (qq * 16 + jl) * PRS + n;
                            #pragma unroll
                            for (int sp = 0; sp < 4; ++sp) v += pq[sp * PPL];
                        }
                        gv[qq] = v;
                    }
                    float ig = fsig_(gv[0]);
                    float fg = fsig_(gv[1]);
                    float gt = ftanh_(gv[2]);
                    float og = fsig_(gv[3]);
                    float cnew = fg * creg[rep] + ig * gt;
                    float hnew = og * ftanh_(cnew);
                    creg[rep] = cnew;
                    hsv[rep]  = hnew;

                    int jcol = g * 16 + jl;
                    size_t sidx = (size_t)nG * 256 + jcol;
                    __nv_bfloat16 hh = __float2bfloat16(hnew);
                    __nv_bfloat16 hl = __float2bfloat16(hnew - __bfloat162float(hh));
                    dhh[sidx] = *(unsigned short*)&hh;
                    dhl[sidx] = *(unsigned short*)&hl;
                }
            }
        }
        __syncthreads();
        if (tid == 0) flag_set(&flags[g * 32], stepBase + (unsigned)(s + 1));

        #pragma unroll
        for (int rep = 0; rep < REPS; ++rep) {
            int e = tid + 512 * rep;
            if (e < ELEM) {
                int n = e >> 4, jl = e & 15;
                int nG = nG0 + n;
                int rr = nG >> 7, bat = nG & 127;
                int time = s * rate + rr;
                int jcol = g * 16 + jl;
                out[((size_t)(layer * TT + time) * BATCH + bat) * Hc + jcol] = hsv[rep];
                if (s + 1 < Td) {
                    int time2 = (s + 1) * rate + rr;
                    const float* gp = g_gx + ((size_t)(time2 * BATCH + bat)) * 1024 + jcol;
                    #pragma unroll
                    for (int qq = 0; qq < 4; ++qq) gxp[rep][qq] = gp[qq * 256];
                }
            }
        }
    }
}

extern "C" void kernel_launch(void* const* d_in, const int* in_sizes, int n_in,
                              void* d_out, int out_size)
{
    const float* x   = (const float*)d_in[0];
    const float* Wih = (const float*)d_in[1];
    const float* Whh = (const float*)d_in[2];
    const float* bih = (const float*)d_in[3];
    const float* bhh = (const float*)d_in[4];
    float* out = (float*)d_out;

    const int gsm   = 2 * BUFSH * 2 + 512;
    const int rsmf1 = 2 * 16 * URS2 * 2 + 4 * 128 * 20 * 4;   // ~58 KB
    const int rsmf2 = 2 * 32 * URS2 * 2 + 4 * 128 * 36 * 4;   // ~107 KB
    const int rsm4  = 2 * 64 * URS2 * 2 + 4 * PPL * 4;
    cudaFuncSetAttribute(gemm_gx, cudaFuncAttributeMaxDynamicSharedMemorySize, gsm);
    cudaFuncSetAttribute(recurF<1>, cudaFuncAttributeMaxDynamicSharedMemorySize, rsmf1);
    cudaFuncSetAttribute(recurF<2>, cudaFuncAttributeMaxDynamicSharedMemorySize, rsmf2);
    cudaFuncSetAttribute(recur<4>,  cudaFuncAttributeMaxDynamicSharedMemorySize, rsm4);

    void *flagp, *xh, *xl, *wh, *wl;
    cudaGetSymbolAddress(&flagp, g_flag);
    cudaGetSymbolAddress(&xh, g_xh);
    cudaGetSymbolAddress(&xl, g_xl);
    cudaGetSymbolAddress(&wh, g_wh);
    cudaGetSymbolAddress(&wl, g_wl);
    cudaMemsetAsync(flagp, 0, 8 * 32 * 32 * sizeof(unsigned), 0);

    const size_t le = (size_t)TT * BATCH * Hc;
    const int n2x = (int)(le / 2);
    const int n2w = 1024 * 256 / 2;
    dim3 ggrid(8, 512);

    // layer 0: fused, 8x8 CTAs x 1024 thr
    presplit<<<n2x / 512, 512>>>(x, (unsigned*)xh, (unsigned*)xl, n2x);
    presplit<<<n2w / 512, 512>>>(Wih, (unsigned*)wh, (unsigned*)wl, n2w);
    gemm_gx<<<ggrid, 512, gsm>>>(bih, bhh);
    recurF<1><<<dim3(8, 8), 1024, rsmf1>>>(Whh, out, 0, 1, 512, 0u);
    // layer 1: fused
    presplit<<<n2x / 512, 512>>>(out, (unsigned*)xh, (unsigned*)xl, n2x);
    presplit<<<n2w / 512, 512>>>(Wih + 1024 * 256, (unsigned*)wh, (unsigned*)wl, n2w);
    gemm_gx<<<ggrid, 512, gsm>>>(bih + 1024, bhh + 1024);
    recurF<2><<<dim3(8, 8), 1024, rsmf2>>>(Whh + 1024 * 256, out, 1, 2, 256, 512u);
    // layer 2: 16x8 CTAs x 512 thr, flag bank 1
    presplit<<<n2x / 512, 512>>>(out + le, (unsigned*)xh, (unsigned*)xl, n2x);
    presplit<<<n2w / 512, 512>>>(Wih + 2 * 1024 * 256, (unsigned*)wh, (unsigned*)wl, n2w);
    gemm_gx<<<ggrid, 512, gsm>>>(bih + 2048, bhh + 2048);
    recur<4><<<dim3(16, 8), 512, rsm4>>>(Whh + 2 * 1024 * 256, out, 2, 4, 128, 0u);
}

// round 17
// speedup vs baseline: 1.4188x; 1.4188x over previous
#include <cuda_runtime.h>
#include <cuda_bf16.h>
#include <cuda_fp16.h>
#include <cstdint>
#include <math.h>

// 3 stacked dilated LSTM layers (rates 1,2,4), T=512, B=128, H=D=256, fp32 I/O.
// presplit(X,W) -> gemm gx = X@Wih^T + b (cp.async, bf16 3-term) ->
// recurrent scan: HMMA fp16, Whh 2-term fp16 split x single-plane fp16 h
// (2 MMAs/k-tile); per-k-slice producer flags; MUFU-approx pointwise.

#define Hc    256
#define BATCH 128
#define TT    512
#define URS2  264            // u row stride (fp16 elems)
#define PRS   68             // part row stride (floats)
#define PPL   (64 * PRS)
#define GXS   72             // gemm smem k-stride (shorts)
#define BUFSH (4 * 128 * GXS)

__device__ float          g_gx[(size_t)TT * BATCH * 1024];   // 256 MB
__device__ unsigned short g_hf[2][512 * 256];                // h plane (fp16)
__device__ unsigned short g_xh[(size_t)TT * BATCH * 256];
__device__ unsigned short g_xl[(size_t)TT * BATCH * 256];
__device__ unsigned short g_wh[1024 * 256];
__device__ unsigned short g_wl[1024 * 256];
__device__ unsigned       g_flag[8][16 * 32];                // 128B-apart flags

__device__ __forceinline__ void flag_set(unsigned* p, unsigned v) {
    asm volatile("st.release.gpu.global.u32 [%0], %1;" :: "l"(p), "r"(v) : "memory");
}
__device__ __forceinline__ unsigned flag_get(unsigned* p) {
    unsigned v;
    asm volatile("ld.acquire.gpu.global.u32 %0, [%1];" : "=r"(v) : "l"(p) : "memory");
    return v;
}
__device__ __forceinline__ unsigned smem_u32(const void* p) {
    unsigned a;
    asm("{ .reg .u64 t; cvta.to.shared.u64 t, %1; cvt.u32.u64 %0, t; }"
        : "=r"(a) : "l"(p));
    return a;
}
__device__ __forceinline__ void cp16(unsigned dst, const void* src) {
    asm volatile("cp.async.ca.shared.global [%0], [%1], 16;"
                 :: "r"(dst), "l"(src) : "memory");
}
__device__ __forceinline__ float ftanh_(float x) {
    float y;
    asm("tanh.approx.f32 %0, %1;" : "=f"(y) : "f"(x));
    return y;
}
__device__ __forceinline__ float fsig_(float x) {
    float e, y;
    asm("ex2.approx.ftz.f32 %0, %1;" : "=f"(e) : "f"(-1.4426950408889634f * x));
    asm("rcp.approx.ftz.f32 %0, %1;" : "=f"(y) : "f"(1.0f + e));
    return y;
}
// bf16 split (gemm path)
__device__ __forceinline__ void split_pack(float x, float y,
                                           unsigned& hi, unsigned& lo) {
    __nv_bfloat162 h2, l2;
    h2.x = __float2bfloat16(x);
    h2.y = __float2bfloat16(y);
    l2.x = __float2bfloat16(x - __bfloat162float(h2.x));
    l2.y = __float2bfloat16(y - __bfloat162float(h2.y));
    hi = *(unsigned*)&h2;
    lo = *(unsigned*)&l2;
}
// fp16 split (recur Whh path)
__device__ __forceinline__ void split_pack_f16(float x, float y,
                                               unsigned& hi, unsigned& lo) {
    __half2 h2, l2;
    h2.x = __float2half(x);
    h2.y = __float2half(y);
    l2.x = __float2half(x - __half2float(h2.x));
    l2.y = __float2half(y - __half2float(h2.y));
    hi = *(unsigned*)&h2;
    lo = *(unsigned*)&l2;
}
__device__ __forceinline__ void mma16816(float d[4], const unsigned a[4],
                                         unsigned b0, unsigned b1) {
    asm volatile(
        "mma.sync.aligned.m16n8k16.row.col.f32.bf16.bf16.f32 "
        "{%0,%1,%2,%3},{%4,%5,%6,%7},{%8,%9},{%0,%1,%2,%3};"
        : "+f"(d[0]), "+f"(d[1]), "+f"(d[2]), "+f"(d[3])
        : "r"(a[0]), "r"(a[1]), "r"(a[2]), "r"(a[3]), "r"(b0), "r"(b1));
}
__device__ __forceinline__ void mma16816h(float d[4], const unsigned a[4],
                                          unsigned b0, unsigned b1) {
    asm volatile(
        "mma.sync.aligned.m16n8k16.row.col.f32.f16.f16.f32 "
        "{%0,%1,%2,%3},{%4,%5,%6,%7},{%8,%9},{%0,%1,%2,%3};"
        : "+f"(d[0]), "+f"(d[1]), "+f"(d[2]), "+f"(d[3])
        : "r"(a[0]), "r"(a[1]), "r"(a[2]), "r"(a[3]), "r"(b0), "r"(b1));
}

// ============================================================================
// presplit: fp32 -> bf16 hi/lo planes (gemm inputs)
// ============================================================================
extern "C" __global__ void __launch_bounds__(512, 2)
presplit(const float* __restrict__ src, unsigned* __restrict__ dh,
         unsigned* __restrict__ dl, int n2)
{
    int i = blockIdx.x * 512 + threadIdx.x;
    if (i < n2) {
        float2 v = ((const float2*)src)[i];
        unsigned h, l;
        split_pack(v.x, v.y, h, l);
        dh[i] = h;
        dl[i] = l;
    }
}

// ============================================================================
// gemm: g_gx[row, R] = sum_k X[row,k]*W[R,k] + b1[R] + b2[R]
// grid (8, 512), cp.async 2-stage k-panel pipeline (bf16 3-term split)
// ============================================================================
extern "C" __global__ void __launch_bounds__(512, 1)
gemm_gx(const float* __restrict__ b1, const float* __restrict__ b2)
{
    extern __shared__ char smraw[];
    unsigned short* buf = (unsigned short*)smraw;
    float* bias_s = (float*)(buf + 2 * BUFSH);
    const unsigned sbase = smem_u32(smraw);

    const int bn = blockIdx.x, bm = blockIdx.y;
    const int tid  = threadIdx.x;
    const int wid  = tid >> 5, lane = tid & 31;
    const int wm   = wid >> 2, wn = wid & 3;
    const int gid  = lane >> 2, t4 = lane & 3;

    if (tid < 128) bias_s[tid] = b1[bn * 128 + tid] + b2[bn * 128 + tid];

    float dd[2][4][4];
    #pragma unroll
    for (int mt = 0; mt < 2; ++mt)
        #pragma unroll
        for (int nt = 0; nt < 4; ++nt)
            #pragma unroll
            for (int r = 0; r < 4; ++r) dd[mt][nt][r] = 0.f;

    const int r_ld = tid >> 2;
    const int p_ld = tid & 3;
    const size_t xoff = (size_t)(bm * 128 + r_ld) * 256;
    const size_t woff = (size_t)(bn * 128 + r_ld) * 256;

    auto prefetch = [&](int kp, int stage) {
        int kg = kp * 64 + p_ld * 16;
        int kl = p_ld * 16;
        unsigned db = sbase + (unsigned)(stage * BUFSH * 2);
        unsigned ro = (unsigned)((r_ld * GXS + kl) * 2);
        cp16(db + 0 * 128 * GXS * 2 + ro,      g_xh + xoff + kg);
        cp16(db + 0 * 128 * GXS * 2 + ro + 16, g_xh + xoff + kg + 8);
        cp16(db + 1 * 128 * GXS * 2 + ro,      g_xl + xoff + kg);
        cp16(db + 1 * 128 * GXS * 2 + ro + 16, g_xl + xoff + kg + 8);
        cp16(db + 2 * 128 * GXS * 2 + ro,      g_wh + woff + kg);
        cp16(db + 2 * 128 * GXS * 2 + ro + 16, g_wh + woff + kg + 8);
        cp16(db + 3 * 128 * GXS * 2 + ro,      g_wl + woff + kg);
        cp16(db + 3 * 128 * GXS * 2 + ro + 16, g_wl + woff + kg + 8);
        asm volatile("cp.async.commit_group;" ::: "memory");
    };

    prefetch(0, 0);

    for (int kp = 0; kp < 4; ++kp) {
        if (kp < 3) prefetch(kp + 1, (kp + 1) & 1);
        if (kp < 3) asm volatile("cp.async.wait_group 1;" ::: "memory");
        else        asm volatile("cp.async.wait_group 0;" ::: "memory");
        __syncthreads();

        unsigned short* Xh = buf + (kp & 1) * BUFSH;
        unsigned short* Xl = Xh + 128 * GXS;
        unsigned short* Wh = Xl + 128 * GXS;
        unsigned short* Wl = Wh + 128 * GXS;

        #pragma unroll
        for (int i = 0; i < 4; ++i) {
            int k0 = i * 16 + t4 * 2;
            unsigned ah[2][4], al[2][4];
            #pragma unroll
            for (int mt = 0; mt < 2; ++mt) {
                int r0 = wm * 32 + mt * 16;
                ah[mt][0] = *(unsigned*)(Xh + (r0 + gid)     * GXS + k0);
                ah[mt][1] = *(unsigned*)(Xh + (r0 + gid + 8) * GXS + k0);
                ah[mt][2] = *(unsigned*)(Xh + (r0 + gid)     * GXS + k0 + 8);
                ah[mt][3] = *(unsigned*)(Xh + (r0 + gid + 8) * GXS + k0 + 8);
                al[mt][0] = *(unsigned*)(Xl + (r0 + gid)     * GXS + k0);
                al[mt][1] = *(unsigned*)(Xl + (r0 + gid + 8) * GXS + k0);
                al[mt][2] = *(unsigned*)(Xl + (r0 + gid)     * GXS + k0 + 8);
                al[mt][3] = *(unsigned*)(Xl + (r0 + gid + 8) * GXS + k0 + 8);
            }
            #pragma unroll
            for (int nt = 0; nt < 4; ++nt) {
                int n0 = wn * 32 + nt * 8;
                unsigned bh0 = *(unsigned*)(Wh + (n0 + gid) * GXS + k0);
                unsigned bh1 = *(unsigned*)(Wh + (n0 + gid) * GXS + k0 + 8);
                unsigned bl0 = *(unsigned*)(Wl + (n0 + gid) * GXS + k0);
                unsigned bl1 = *(unsigned*)(Wl + (n0 + gid) * GXS + k0 + 8);
                #pragma unroll
                for (int mt = 0; mt < 2; ++mt) {
                    mma16816(dd[mt][nt], ah[mt], bh0, bh1);
                    mma16816(dd[mt][nt], ah[mt], bl0, bl1);
                    mma16816(dd[mt][nt], al[mt], bh0, bh1);
                }
            }
        }
        __syncthreads();
    }

    #pragma unroll
    for (int mt = 0; mt < 2; ++mt)
        #pragma unroll
        for (int nt = 0; nt < 4; ++nt) {
            int rowA = bm * 128 + wm * 32 + mt * 16 + gid;
            int cl   = wn * 32 + nt * 8 + 2 * t4;
            int col  = bn * 128 + cl;
            float bx = bias_s[cl], by = bias_s[cl + 1];
            *(float2*)(g_gx + (size_t)rowA * 1024 + col) =
                make_float2(dd[mt][nt][0] + bx, dd[mt][nt][1] + by);
            *(float2*)(g_gx + (size_t)(rowA + 8) * 1024 + col) =
                make_float2(dd[mt][nt][2] + bx, dd[mt][nt][3] + by);
        }
}

// ============================================================================
// recur: grid (16 gate-CTAs, 8 batch-blocks), 512 threads. NT16 = Nper/16.
// fp16: Whh 2-term split, h single plane -> 2 MMAs per k-tile per n-half.
// ============================================================================
template<int NT16>
__global__ void __launch_bounds__(512, 1)
recur(const float* __restrict__ WhhL, float* __restrict__ out,
      int layer, int rate, int Td, unsigned stepBase)
{
    constexpr int Nper = NT16 * 16;
    constexpr int ELEM = NT16 * 256;
    constexpr int REPS = (ELEM + 511) / 512;

    extern __shared__ char smraw[];
    unsigned short* u_s = (unsigned short*)smraw;         // Nper x URS2 (fp16)
    float* part = (float*)(smraw + (size_t)Nper * URS2 * 2);  // 4 x PPL

    const int g   = blockIdx.x;
    const int nb  = blockIdx.y;
    const int tid = threadIdx.x;
    const int wid = tid >> 5, lane = tid & 31;
    const int q   = wid & 3;
    const int ks  = wid >> 2;
    const int gid = lane >> 2, t4 = lane & 3;
    const int nG0 = nb * Nper;

    // stationary A fragments from Whh (K=256), fp16 hi/lo
    unsigned a_hi[4][4], a_lo[4][4];
    {
        const int rowT = q * 256 + g * 16 + gid;
        const int rowB = rowT + 8;
        #pragma unroll
        for (int i = 0; i < 4; ++i) {
            int kb = (ks * 4 + i) * 16 + t4 * 2;
            #pragma unroll
            for (int r = 0; r < 4; ++r) {
                int row = (r & 1) ? rowB : rowT;
                int k   = kb + ((r >> 1) ? 8 : 0);
                float2 v = *(const float2*)(WhhL + (size_t)row * 256 + k);
                split_pack_f16(v.x, v.y, a_hi[i][r], a_lo[i][r]);
            }
        }
    }

    unsigned* flags = &g_flag[nb][0];

    float gxp[REPS][4], creg[REPS], hsv[REPS];
    #pragma unroll
    for (int rep = 0; rep < REPS; ++rep) creg[rep] = 0.f;

    // prefetch gx for step 0
    #pragma unroll
    for (int rep = 0; rep < REPS; ++rep) {
        int e = tid + 512 * rep;
        if (e < ELEM) {
            int n = e >> 4, jl = e & 15;
            int nG = nG0 + n;
            int rr = nG >> 7, bat = nG & 127;
            const float* gp = g_gx + ((size_t)(rr * BATCH + bat)) * 1024 + g * 16 + jl;
            #pragma unroll
            for (int qq = 0; qq < 4; ++qq) gxp[rep][qq] = gp[qq * 256];
        }
    }

    for (int s = 0; s < Td; ++s) {
        if (s > 0) {
            // per-warp: wait only for the 4 producer CTAs of k-slice ks
            if (lane < 4) {
                unsigned target = stepBase + (unsigned)s;
                while (flag_get(&flags[(4 * ks + lane) * 32]) < target) { }
            }
            __syncwarp();

            // ---- stage rows [q*4*NT16, +4*NT16), k-slice [64ks, 64ks+64)
            {
                const unsigned short* shf = g_hf[(s + 1) & 1];
                #pragma unroll
                for (int it = 0; it < NT16; ++it) {
                    int row  = q * 4 * NT16 + it * 4 + (lane >> 3);
                    int kpos = ks * 64 + (lane & 7) * 8;
                    int nG   = nG0 + row;
                    uint4 vh = *(const uint4*)(shf + (size_t)nG * 256 + kpos);
                    *(uint4*)(u_s + row * URS2 + kpos) = vh;
                }
            }
            // sync the 4 warps of this ks-group (barrier ids 1..4)
            asm volatile("bar.sync %0, %1;" :: "r"(1 + ks), "r"(128) : "memory");

            // ---- HMMA fp16: part = h @ Whh^T (2-term split), k-slice ks
            {
                float dd[NT16][8];
                #pragma unroll
                for (int nt = 0; nt < NT16; ++nt)
                    #pragma unroll
                    for (int r = 0; r < 8; ++r) dd[nt][r] = 0.f;

                #pragma unroll
                for (int i = 0; i < 4; ++i) {
                    int kof = (ks * 4 + i) * 16 + t4 * 2;
                    #pragma unroll
                    for (int nt = 0; nt < NT16; ++nt) {
                        const unsigned short* uh = u_s + (nt * 16 + gid) * URS2 + kof;
                        unsigned b0a = *(const unsigned*)uh;
                        unsigned b0b = *(const unsigned*)(uh + 8);
                        unsigned b8a = *(const unsigned*)(uh + 8 * URS2);
                        unsigned b8b = *(const unsigned*)(uh + 8 * URS2 + 8);
                        mma16816h(dd[nt] + 0, a_hi[i], b0a, b0b);
                        mma16816h(dd[nt] + 0, a_lo[i], b0a, b0b);
                        mma16816h(dd[nt] + 4, a_hi[i], b8a, b8b);
                        mma16816h(dd[nt] + 4, a_lo[i], b8a, b8b);
                    }
                }

                #pragma unroll
                for (int nt = 0; nt < NT16; ++nt) {
                    float* pp = part + ks * PPL + (q * 16) * PRS + nt * 16;
                    *(float2*)(pp + gid * PRS + 2 * t4)           = make_float2(dd[nt][0], dd[nt][1]);
                    *(float2*)(pp + (gid + 8) * PRS + 2 * t4)     = make_float2(dd[nt][2], dd[nt][3]);
                    *(float2*)(pp + gid * PRS + 8 + 2 * t4)       = make_float2(dd[nt][4], dd[nt][5]);
                    *(float2*)(pp + (gid + 8) * PRS + 8 + 2 * t4) = make_float2(dd[nt][6], dd[nt][7]);
                }
            }
            __syncthreads();
        }

        // ---- pointwise: gates = gx + sum(part); c,h in regs; store h plane
        {
            unsigned short* dhf = g_hf[s & 1];
            #pragma unroll
            for (int rep = 0; rep < REPS; ++rep) {
                int e = tid + 512 * rep;
                if (e < ELEM) {
                    int n = e >> 4, jl = e & 15;
                    int nG = nG0 + n;
                    float gv[4];
                    #pragma unroll
                    for (int qq = 0; qq < 4; ++qq) {
                        float v = gxp[rep][qq];
                        if (s > 0) {
                            const float* pq = part + (qq * 16 + jl) * PRS + n;
                            #pragma unroll
                            for (int sp = 0; sp < 4; ++sp) v += pq[sp * PPL];
                        }
                        gv[qq] = v;
                    }
                    float ig = fsig_(gv[0]);
                    float fg = fsig_(gv[1]);
                    float gt = ftanh_(gv[2]);
                    float og = fsig_(gv[3]);
                    float cnew = fg * creg[rep] + ig * gt;
                    float hnew = og * ftanh_(cnew);
                    creg[rep] = cnew;
                    hsv[rep]  = hnew;

                    int jcol = g * 16 + jl;
                    __half hh = __float2half(hnew);
                    dhf[(size_t)nG * 256 + jcol] = *(unsigned short*)&hh;
                }
            }
        }
        __syncthreads();
        if (tid == 0) flag_set(&flags[g * 32], stepBase + (unsigned)(s + 1));

        // ---- shadowed behind barrier: out stores + next-step gx prefetch
        #pragma unroll
        for (int rep = 0; rep < REPS; ++rep) {
            int e = tid + 512 * rep;
            if (e < ELEM) {
                int n = e >> 4, jl = e & 15;
                int nG = nG0 + n;
                int rr = nG >> 7, bat = nG & 127;
                int time = s * rate + rr;
                int jcol = g * 16 + jl;
                out[((size_t)(layer * TT + time) * BATCH + bat) * Hc + jcol] = hsv[rep];
                if (s + 1 < Td) {
                    int time2 = (s + 1) * rate + rr;
                    const float* gp = g_gx + ((size_t)(time2 * BATCH + bat)) * 1024 + jcol;
                    #pragma unroll
                    for (int qq = 0; qq < 4; ++qq) gxp[rep][qq] = gp[qq * 256];
                }
            }
        }
    }
}

extern "C" void kernel_launch(void* const* d_in, const int* in_sizes, int n_in,
                              void* d_out, int out_size)
{
    const float* x   = (const float*)d_in[0];
    const float* Wih = (const float*)d_in[1];
    const float* Whh = (const float*)d_in[2];
    const float* bih = (const float*)d_in[3];
    const float* bhh = (const float*)d_in[4];
    float* out = (float*)d_out;

    const int gsm  = 2 * BUFSH * 2 + 512;
    const int rsm1 = 16 * URS2 * 2 + 4 * PPL * 4;
    const int rsm2 = 32 * URS2 * 2 + 4 * PPL * 4;
    const int rsm4 = 64 * URS2 * 2 + 4 * PPL * 4;
    cudaFuncSetAttribute(gemm_gx, cudaFuncAttributeMaxDynamicSharedMemorySize, gsm);
    cudaFuncSetAttribute(recur<1>, cudaFuncAttributeMaxDynamicSharedMemorySize, rsm1);
    cudaFuncSetAttribute(recur<2>, cudaFuncAttributeMaxDynamicSharedMemorySize, rsm2);
    cudaFuncSetAttribute(recur<4>, cudaFuncAttributeMaxDynamicSharedMemorySize, rsm4);

    void *flagp, *xh, *xl, *wh, *wl;
    cudaGetSymbolAddress(&flagp, g_flag);
    cudaGetSymbolAddress(&xh, g_xh);
    cudaGetSymbolAddress(&xl, g_xl);
    cudaGetSymbolAddress(&wh, g_wh);
    cudaGetSymbolAddress(&wl, g_wl);
    cudaMemsetAsync(flagp, 0, 8 * 16 * 32 * sizeof(unsigned), 0);

    const size_t le = (size_t)TT * BATCH * Hc;
    const int n2x = (int)(le / 2);
    const int n2w = 1024 * 256 / 2;
    dim3 ggrid(8, 512), rgrid(16, 8);

    // layer 0
    presplit<<<n2x / 512, 512>>>(x, (unsigned*)xh, (unsigned*)xl, n2x);
    presplit<<<n2w / 512, 512>>>(Wih, (unsigned*)wh, (unsigned*)wl, n2w);
    gemm_gx<<<ggrid, 512, gsm>>>(bih, bhh);
    recur<1><<<rgrid, 512, rsm1>>>(Whh, out, 0, 1, 512, 0u);
    // layer 1
    presplit<<<n2x / 512, 512>>>(out, (unsigned*)xh, (unsigned*)xl, n2x);
    presplit<<<n2w / 512, 512>>>(Wih + 1024 * 256, (unsigned*)wh, (unsigned*)wl, n2w);
    gemm_gx<<<ggrid, 512, gsm>>>(bih + 1024, bhh + 1024);
    recur<2><<<rgrid, 512, rsm2>>>(Whh + 1024 * 256, out, 1, 2, 256, 512u);
    // layer 2
    presplit<<<n2x / 512, 512>>>(out + le, (unsigned*)xh, (unsigned*)xl, n2x);
    presplit<<<n2w / 512, 512>>>(Wih + 2 * 1024 * 256, (unsigned*)wh, (unsigned*)wl, n2w);
    gemm_gx<<<ggrid, 512, gsm>>>(bih + 2048, bhh + 2048);
    recur<4><<<rgrid, 512, rsm4>>>(Whh + 2 * 1024 * 256, out, 2, 4, 128, 768u);
}